// round 8
// baseline (speedup 1.0000x reference)
#include <cuda_runtime.h>
#include <cuda_fp16.h>

#define NMAX 100352
#define EMAX 2000000
#define THREADS 256
#define FULL 0xffffffffu

// ---- scratch (device globals; zero-initialized at module load) ----
// g_deg_* are re-zeroed at the END of each launch (k_scanC) -> every launch
// sees them zeroed -> deterministic, identical work per call.
__device__ __align__(256) int    g_deg_s[NMAX];
__device__ __align__(256) int    g_deg_d[NMAX];
__device__ __align__(256) float  g_ns[NMAX];
__device__ __align__(256) float  g_nd[NMAX];
__device__ __align__(256) int    g_rowstart[NMAX + 1];
__device__ __align__(256) int    g_cursor[NMAX];
__device__ __align__(256) int    g_bsum[256];
__device__ __align__(256) int2   g_csr[EMAX];        // .x = src, .y = bits(ew)
__device__ __align__(256) __half g_hx1[NMAX * 32];   // fp16: ns * (feat @ W1)
__device__ __align__(256) __half g_h2x[NMAX * 16];   // fp16: (relu(.)*ns) @ W2

// K1: integer degree histogram (4 edges/thread)
__global__ void k_deg(const int* __restrict__ src, const int* __restrict__ dst, int e) {
    int t = blockIdx.x * blockDim.x + threadIdx.x;
    int base = t * 4;
    if (base + 3 < e) {
        int4 s4 = *(const int4*)(src + base);
        int4 d4 = *(const int4*)(dst + base);
        atomicAdd(&g_deg_s[s4.x], 1); atomicAdd(&g_deg_s[s4.y], 1);
        atomicAdd(&g_deg_s[s4.z], 1); atomicAdd(&g_deg_s[s4.w], 1);
        atomicAdd(&g_deg_d[d4.x], 1); atomicAdd(&g_deg_d[d4.y], 1);
        atomicAdd(&g_deg_d[d4.z], 1); atomicAdd(&g_deg_d[d4.w], 1);
    } else {
        for (int i = base; i < e; i++) {
            atomicAdd(&g_deg_s[src[i]], 1);
            atomicAdd(&g_deg_d[dst[i]], 1);
        }
    }
}

// K2: per-block (1024 elems) exclusive scan of in-degrees + norms
__global__ void k_scanA(int n) {
    __shared__ int wsum[8];
    int b = blockIdx.x, t = threadIdx.x;
    int base = b * 1024 + t * 4;
    int v[4]; int s = 0;
#pragma unroll
    for (int j = 0; j < 4; j++) {
        v[j] = (base + j < n) ? g_deg_d[base + j] : 0;
        s += v[j];
    }
#pragma unroll
    for (int j = 0; j < 4; j++) {
        int i = base + j;
        if (i < n) {
            g_nd[i] = rsqrtf(fmaxf((float)v[j], 1.0f));
            g_ns[i] = rsqrtf(fmaxf((float)g_deg_s[i], 1.0f));
        }
    }
    int lane = t & 31, wid = t >> 5;
    int incl = s;
#pragma unroll
    for (int o = 1; o < 32; o <<= 1) {
        int x = __shfl_up_sync(FULL, incl, o);
        if (lane >= o) incl += x;
    }
    if (lane == 31) wsum[wid] = incl;
    __syncthreads();
    if (t < 8) {
        int ws = wsum[t];
#pragma unroll
        for (int o = 1; o < 8; o <<= 1) {
            int x = __shfl_up_sync(0xffu, ws, o);
            if ((int)t >= o) ws += x;
        }
        wsum[t] = ws;
    }
    __syncthreads();
    int excl = incl - s + (wid > 0 ? wsum[wid - 1] : 0);
    int run = excl;
#pragma unroll
    for (int j = 0; j < 4; j++) {
        if (base + j < n) g_rowstart[base + j] = run;
        run += v[j];
    }
    if (t == 255) g_bsum[b] = run;
}

// K3: scan block sums (one warp, nb <= 128)
__global__ void k_scanB(int nb, int n, int e) {
    int lane = threadIdx.x;
    int v[4]; int s = 0;
#pragma unroll
    for (int j = 0; j < 4; j++) {
        int idx = lane * 4 + j;
        v[j] = (idx < nb) ? g_bsum[idx] : 0;
        s += v[j];
    }
    int incl = s;
#pragma unroll
    for (int o = 1; o < 32; o <<= 1) {
        int x = __shfl_up_sync(FULL, incl, o);
        if (lane >= o) incl += x;
    }
    int run = incl - s;
#pragma unroll
    for (int j = 0; j < 4; j++) {
        int idx = lane * 4 + j;
        if (idx < nb) g_bsum[idx] = run;
        run += v[j];
    }
    if (lane == 0) g_rowstart[n] = e;
}

// K4: add block offsets; init cursors; re-zero degree tables for next launch
__global__ void k_scanC(int n) {
    int i = blockIdx.x * blockDim.x + threadIdx.x;
    if (i >= n) return;
    int rs = g_rowstart[i] + g_bsum[i >> 10];
    g_rowstart[i] = rs;
    g_cursor[i] = rs;
    g_deg_s[i] = 0;
    g_deg_d[i] = 0;
}

// K5: heterogeneous: blocks [0,FB) fill CSR; blocks [FB,FB+XB) do xform1.
// xform1: g_hx1[n,:] = half( ns[n] * (feat[n,:] @ W1) )
__global__ void __launch_bounds__(THREADS) k_fillx(
        const int* __restrict__ src, const int* __restrict__ dst,
        const float* __restrict__ ew, const float* __restrict__ feat,
        const float* __restrict__ W1, int n, int e, int FB) {
    if ((int)blockIdx.x < FB) {
        int i = blockIdx.x * THREADS + threadIdx.x;
        if (i < e) {
            int s = src[i], d = dst[i];
            float w = __ldg(ew + i);
            int pos = atomicAdd(&g_cursor[d], 1);
            g_csr[pos] = make_int2(s, __float_as_int(w));
        }
        return;
    }
    __shared__ float sf[256 * 33];
    int tid = threadIdx.x;
    int lane = tid & 31, w = tid >> 5;
    float w1[32];
#pragma unroll
    for (int k = 0; k < 32; k++) w1[k] = __ldg(W1 + k * 32 + lane);

    int base = (blockIdx.x - FB) * 256;
    int cnt = min(256, n - base);
    for (int i = tid; i < cnt * 32; i += 256) {
        int node = i >> 5, col = i & 31;
        sf[node * 33 + col] = feat[(size_t)(base + node) * 32 + col];
    }
    __syncthreads();

    for (int t = 0; t < 32; t += 2) {
        int l0 = w * 32 + t, l1 = l0 + 1;
        if (l0 >= cnt) break;
        float acc0 = 0.f, acc1 = 0.f;
        const float* r0 = sf + l0 * 33;
        const float* r1 = sf + l1 * 33;
        bool has1 = (l1 < cnt);
#pragma unroll
        for (int k = 0; k < 32; k++) {
            acc0 = fmaf(r0[k], w1[k], acc0);
            acc1 = fmaf(r1[k], w1[k], acc1);
        }
        int n0 = base + l0;
        g_hx1[(size_t)n0 * 32 + lane] = __float2half_rn(acc0 * g_ns[n0]);
        if (has1) g_hx1[(size_t)(n0 + 1) * 32 + lane] = __float2half_rn(acc1 * g_ns[n0 + 1]);
    }
}

// K6: gather layer 1 (fp16 rows, 64B) + fused xform2 -> g_h2x (fp16)
//   agg = seg_sum(ew * hx1[src]); h = relu(nd*agg + b1)*ns; h2x = h @ W2
// 8 subgroups x 4 lanes; lane loads one 16B chunk (8 halfs); fp32 accum.
__global__ void __launch_bounds__(THREADS) k_gather1(
        const float* __restrict__ b1, const float* __restrict__ W2, int n) {
    __shared__ float sW2[512];   // 32 x 16
    __shared__ float sb1[32];
    int tid = threadIdx.x;
    for (int i = tid; i < 512; i += THREADS) sW2[i] = __ldg(W2 + i);
    for (int i = tid; i < 32;  i += THREADS) sb1[i] = __ldg(b1 + i);
    __syncthreads();

    int lane = tid & 31;
    int sub = lane >> 2;        // 0..7
    int comp = lane & 3;        // 16B chunk id within 64B row
    int j = lane & 15;

    int warpId = (blockIdx.x * blockDim.x + tid) >> 5;
    int nwarps = (gridDim.x * blockDim.x) >> 5;

    for (int node = warpId; node < n; node += nwarps) {
        int rs = g_rowstart[node], re = g_rowstart[node + 1];
        float a[8];
#pragma unroll
        for (int q = 0; q < 8; q++) a[q] = 0.f;

        for (int base = rs; base < re; base += 16) {
#pragma unroll
            for (int u = 0; u < 2; u++) {
                int i = base + u * 8 + sub;
                if (i < re) {
                    int2 eg = g_csr[i];
                    float wt = __int_as_float(eg.y);
                    uint4 c = ((const uint4*)(g_hx1 + (size_t)eg.x * 32))[comp];
                    float2 p;
                    p = __half22float2(*(__half2*)&c.x);
                    a[0] = fmaf(wt, p.x, a[0]); a[1] = fmaf(wt, p.y, a[1]);
                    p = __half22float2(*(__half2*)&c.y);
                    a[2] = fmaf(wt, p.x, a[2]); a[3] = fmaf(wt, p.y, a[3]);
                    p = __half22float2(*(__half2*)&c.z);
                    a[4] = fmaf(wt, p.x, a[4]); a[5] = fmaf(wt, p.y, a[5]);
                    p = __half22float2(*(__half2*)&c.w);
                    a[6] = fmaf(wt, p.x, a[6]); a[7] = fmaf(wt, p.y, a[7]);
                }
            }
        }
        // reduce across the 8 subgroups (xor 4,8,16): all lanes end with the
        // full aggregate for their comp.
#pragma unroll
        for (int o = 4; o < 32; o <<= 1)
#pragma unroll
            for (int q = 0; q < 8; q++)
                a[q] += __shfl_xor_sync(FULL, a[q], o);

        float nd = g_nd[node];
        float ns = g_ns[node];
        float h[8];
#pragma unroll
        for (int q = 0; q < 8; q++)
            h[q] = fmaxf(fmaf(a[q], nd, sb1[comp * 8 + q]), 0.f) * ns;

        // fused 32->16 GEMM: y_j = sum_k h_k * W2[k][j]; h_k (k = m*8+q) lives
        // on lane m (m = 0..3 have comp == m).
        float y = 0.f;
#pragma unroll
        for (int m = 0; m < 4; m++) {
#pragma unroll
            for (int q = 0; q < 8; q++) {
                float hv = __shfl_sync(FULL, h[q], m);
                y = fmaf(hv, sW2[(m * 8 + q) * 16 + j], y);
            }
        }
        if (lane < 16) g_h2x[(size_t)node * 16 + j] = __float2half_rn(y);
    }
}

// K7: gather layer 2 (fp16 rows, 32B): out = nd * seg_sum(ew * h2x[src]) + b2
// 16 subgroups x 2 lanes; lane loads one 16B chunk (8 halfs); fp32 accum.
__global__ void __launch_bounds__(THREADS) k_gather2(const float* __restrict__ b2,
                                                     float* __restrict__ out, int n) {
    int lane = threadIdx.x & 31;
    int sub = lane >> 1;        // 0..15
    int comp = lane & 1;        // 16B chunk id within 32B row
    float bb[8];
#pragma unroll
    for (int q = 0; q < 8; q++) bb[q] = __ldg(b2 + comp * 8 + q);

    int warpId = (blockIdx.x * blockDim.x + threadIdx.x) >> 5;
    int nwarps = (gridDim.x * blockDim.x) >> 5;

    for (int node = warpId; node < n; node += nwarps) {
        int rs = g_rowstart[node], re = g_rowstart[node + 1];
        float a[8];
#pragma unroll
        for (int q = 0; q < 8; q++) a[q] = 0.f;

        for (int base = rs; base < re; base += 32) {
#pragma unroll
            for (int u = 0; u < 2; u++) {
                int i = base + u * 16 + sub;
                if (i < re) {
                    int2 eg = g_csr[i];
                    float wt = __int_as_float(eg.y);
                    uint4 c = ((const uint4*)(g_h2x + (size_t)eg.x * 16))[comp];
                    float2 p;
                    p = __half22float2(*(__half2*)&c.x);
                    a[0] = fmaf(wt, p.x, a[0]); a[1] = fmaf(wt, p.y, a[1]);
                    p = __half22float2(*(__half2*)&c.y);
                    a[2] = fmaf(wt, p.x, a[2]); a[3] = fmaf(wt, p.y, a[3]);
                    p = __half22float2(*(__half2*)&c.z);
                    a[4] = fmaf(wt, p.x, a[4]); a[5] = fmaf(wt, p.y, a[5]);
                    p = __half22float2(*(__half2*)&c.w);
                    a[6] = fmaf(wt, p.x, a[6]); a[7] = fmaf(wt, p.y, a[7]);
                }
            }
        }
        // reduce across the 16 subgroups (xor 2,4,8,16)
#pragma unroll
        for (int o = 2; o < 32; o <<= 1)
#pragma unroll
            for (int q = 0; q < 8; q++)
                a[q] += __shfl_xor_sync(FULL, a[q], o);

        if (lane < 2) {
            float nd = g_nd[node];
            float4 y0, y1;
            y0.x = fmaf(a[0], nd, bb[0]); y0.y = fmaf(a[1], nd, bb[1]);
            y0.z = fmaf(a[2], nd, bb[2]); y0.w = fmaf(a[3], nd, bb[3]);
            y1.x = fmaf(a[4], nd, bb[4]); y1.y = fmaf(a[5], nd, bb[5]);
            y1.z = fmaf(a[6], nd, bb[6]); y1.w = fmaf(a[7], nd, bb[7]);
            float4* orow = (float4*)(out + (size_t)node * 16);
            orow[comp * 2 + 0] = y0;
            orow[comp * 2 + 1] = y1;
        }
    }
}

static inline int cdiv(long long a, int b) { return (int)((a + b - 1) / b); }

extern "C" void kernel_launch(void* const* d_in, const int* in_sizes, int n_in,
                              void* d_out, int out_size) {
    const float* feat = (const float*)d_in[0];
    const int*   src  = (const int*)d_in[1];
    const int*   dst  = (const int*)d_in[2];
    const float* ew   = (const float*)d_in[3];
    const float* W1   = (const float*)d_in[4];
    const float* b1   = (const float*)d_in[5];
    const float* W2   = (const float*)d_in[6];
    const float* b2   = (const float*)d_in[7];
    float* out = (float*)d_out;

    int n = in_sizes[0] / 32;
    int e = in_sizes[1];
    int nb = cdiv(n, 1024);
    int FB = cdiv(e, THREADS);       // fill blocks
    int XB = cdiv(n, 256);           // xform1 blocks

    const int GBLOCKS = 592;  // 4 blocks/SM

    k_deg    <<<cdiv(cdiv(e, 4), THREADS), THREADS>>>(src, dst, e);
    k_scanA  <<<nb, THREADS>>>(n);
    k_scanB  <<<1, 32>>>(nb, n, e);
    k_scanC  <<<cdiv(n, THREADS), THREADS>>>(n);
    k_fillx  <<<FB + XB, THREADS>>>(src, dst, ew, feat, W1, n, e, FB);
    k_gather1<<<GBLOCKS, THREADS>>>(b1, W2, n);
    k_gather2<<<GBLOCKS, THREADS>>>(b2, out, n);
}

// round 9
// speedup vs baseline: 1.1995x; 1.1995x over previous
#include <cuda_runtime.h>
#include <cuda_bf16.h>

#define NMAX 100352
#define THREADS 256
#define FULL 0xffffffffu

// ---- scratch (device globals; zero-initialized at module load) ----
// g_deg_* are re-zeroed inside k_prep each launch -> deterministic.
__device__ __align__(256) int   g_deg_s[NMAX];
__device__ __align__(256) int   g_deg_d[NMAX];
__device__ __align__(256) float g_ns[NMAX];
__device__ __align__(256) float g_nd[NMAX];
__device__ __align__(256) float g_hx1[NMAX * 32];   // ns * (feat @ W1)
__device__ __align__(256) float g_agg1[NMAX * 32];  // RED accumulator (pre-nd)
__device__ __align__(256) float g_h2x[NMAX * 16];   // (relu(nd*agg+b1)*ns) @ W2

// K1: integer degree histogram (4 edges/thread)
__global__ void k_deg(const int* __restrict__ src, const int* __restrict__ dst, int e) {
    int t = blockIdx.x * blockDim.x + threadIdx.x;
    int base = t * 4;
    if (base + 3 < e) {
        int4 s4 = *(const int4*)(src + base);
        int4 d4 = *(const int4*)(dst + base);
        atomicAdd(&g_deg_s[s4.x], 1); atomicAdd(&g_deg_s[s4.y], 1);
        atomicAdd(&g_deg_s[s4.z], 1); atomicAdd(&g_deg_s[s4.w], 1);
        atomicAdd(&g_deg_d[d4.x], 1); atomicAdd(&g_deg_d[d4.y], 1);
        atomicAdd(&g_deg_d[d4.z], 1); atomicAdd(&g_deg_d[d4.w], 1);
    } else {
        for (int i = base; i < e; i++) {
            atomicAdd(&g_deg_s[src[i]], 1);
            atomicAdd(&g_deg_d[dst[i]], 1);
        }
    }
}

// K2: fused prep over grid of n*8 threads:
//  t < n*8 : zero g_agg1 (float4 lanes, coalesced)
//  t < n*4 : out[t] = b2 broadcast (float4)
//  t < n   : norms from degrees; re-zero degree tables for next launch
__global__ void k_prep(float* __restrict__ out, const float* __restrict__ b2, int n) {
    int t = blockIdx.x * blockDim.x + threadIdx.x;
    if (t < n * 8) ((float4*)g_agg1)[t] = make_float4(0.f, 0.f, 0.f, 0.f);
    if (t < n * 4) ((float4*)out)[t] = ((const float4*)b2)[t & 3];
    if (t < n) {
        g_ns[t] = rsqrtf(fmaxf((float)g_deg_s[t], 1.0f));
        g_nd[t] = rsqrtf(fmaxf((float)g_deg_d[t], 1.0f));
        g_deg_s[t] = 0;
        g_deg_d[t] = 0;
    }
}

// K3: xform1 (smem staged): g_hx1[n,:] = ns[n] * (feat[n,:] @ W1)
__global__ void __launch_bounds__(THREADS) k_xform1(const float* __restrict__ feat,
                                                    const float* __restrict__ W1, int n) {
    __shared__ float sf[256 * 33];
    int tid = threadIdx.x;
    int lane = tid & 31, w = tid >> 5;
    float w1[32];
#pragma unroll
    for (int k = 0; k < 32; k++) w1[k] = __ldg(W1 + k * 32 + lane);

    int base = blockIdx.x * 256;
    int cnt = min(256, n - base);
    for (int i = tid; i < cnt * 32; i += 256) {
        int node = i >> 5, col = i & 31;
        sf[node * 33 + col] = feat[(size_t)(base + node) * 32 + col];
    }
    __syncthreads();

    for (int t = 0; t < 32; t += 2) {
        int l0 = w * 32 + t, l1 = l0 + 1;
        if (l0 >= cnt) break;
        float acc0 = 0.f, acc1 = 0.f;
        const float* r0 = sf + l0 * 33;
        const float* r1 = sf + l1 * 33;
        bool has1 = (l1 < cnt);
#pragma unroll
        for (int k = 0; k < 32; k++) {
            acc0 = fmaf(r0[k], w1[k], acc0);
            acc1 = fmaf(r1[k], w1[k], acc1);
        }
        int n0 = base + l0;
        g_hx1[(size_t)n0 * 32 + lane] = acc0 * g_ns[n0];
        if (has1) g_hx1[(size_t)(n0 + 1) * 32 + lane] = acc1 * g_ns[n0 + 1];
    }
}

// K4: edge RED layer 1: 8 threads/edge, float4 each; nd applied later in xform2.
__global__ void k_edge1(const int* __restrict__ src, const int* __restrict__ dst,
                        const float* __restrict__ ew, int e) {
    int t = blockIdx.x * blockDim.x + threadIdx.x;
    if (t >= e * 8) return;
    int eid = t >> 3;
    int c = t & 7;
    int s = __ldg(src + eid);
    int d = __ldg(dst + eid);
    float w = __ldg(ew + eid);
    float4 v = *(const float4*)(g_hx1 + (size_t)s * 32 + c * 4);
    v.x *= w; v.y *= w; v.z *= w; v.w *= w;
    float* p = g_agg1 + (size_t)d * 32 + c * 4;
    asm volatile("red.global.add.v4.f32 [%0], {%1,%2,%3,%4};"
                 :: "l"(p), "f"(v.x), "f"(v.y), "f"(v.z), "f"(v.w)
                 : "memory");
}

// K5: xform2 (smem staged): h = relu(nd*agg + b1) * ns; g_h2x = h @ W2
// elementwise transform applied while staging into smem; half-warp per node.
__global__ void __launch_bounds__(THREADS) k_xform2(const float* __restrict__ W2,
                                                    const float* __restrict__ b1, int n) {
    __shared__ float sf[256 * 33];
    __shared__ float sb1[32];
    int tid = threadIdx.x;
    int lane = tid & 31, w = tid >> 5;
    int p = lane >> 4, j = lane & 15;
    for (int i = tid; i < 32; i += 256) sb1[i] = __ldg(b1 + i);
    float w2[32];
#pragma unroll
    for (int k = 0; k < 32; k++) w2[k] = __ldg(W2 + k * 16 + j);
    __syncthreads();

    int base = blockIdx.x * 256;
    int cnt = min(256, n - base);
    for (int i = tid; i < cnt * 32; i += 256) {
        int node = i >> 5, col = i & 31;
        int gn = base + node;
        float a = g_agg1[(size_t)gn * 32 + col];
        sf[node * 33 + col] = fmaxf(fmaf(a, g_nd[gn], sb1[col]), 0.f) * g_ns[gn];
    }
    __syncthreads();

    for (int t = 0; t < 32; t += 2) {
        int l = w * 32 + t + p;
        if (l >= cnt) continue;
        float acc = 0.f;
        const float* r = sf + l * 33;
#pragma unroll
        for (int k = 0; k < 32; k++) acc = fmaf(r[k], w2[k], acc);
        g_h2x[(size_t)(base + l) * 16 + j] = acc;
    }
}

// K6: edge RED layer 2: 4 threads/edge; nd[d] folded into weight; out pre-inited to b2.
__global__ void k_edge2(const int* __restrict__ src, const int* __restrict__ dst,
                        const float* __restrict__ ew, float* __restrict__ out, int e) {
    int t = blockIdx.x * blockDim.x + threadIdx.x;
    if (t >= e * 4) return;
    int eid = t >> 2;
    int c = t & 3;
    int s = __ldg(src + eid);
    int d = __ldg(dst + eid);
    float w = __ldg(ew + eid) * g_nd[d];
    float4 v = *(const float4*)(g_h2x + (size_t)s * 16 + c * 4);
    v.x *= w; v.y *= w; v.z *= w; v.w *= w;
    float* p = out + (size_t)d * 16 + c * 4;
    asm volatile("red.global.add.v4.f32 [%0], {%1,%2,%3,%4};"
                 :: "l"(p), "f"(v.x), "f"(v.y), "f"(v.z), "f"(v.w)
                 : "memory");
}

static inline int cdiv(long long a, int b) { return (int)((a + b - 1) / b); }

extern "C" void kernel_launch(void* const* d_in, const int* in_sizes, int n_in,
                              void* d_out, int out_size) {
    const float* feat = (const float*)d_in[0];
    const int*   src  = (const int*)d_in[1];
    const int*   dst  = (const int*)d_in[2];
    const float* ew   = (const float*)d_in[3];
    const float* W1   = (const float*)d_in[4];
    const float* b1   = (const float*)d_in[5];
    const float* W2   = (const float*)d_in[6];
    const float* b2   = (const float*)d_in[7];
    float* out = (float*)d_out;

    int n = in_sizes[0] / 32;
    int e = in_sizes[1];

    k_deg   <<<cdiv(cdiv(e, 4), THREADS), THREADS>>>(src, dst, e);
    k_prep  <<<cdiv((long long)n * 8, THREADS), THREADS>>>(out, b2, n);
    k_xform1<<<cdiv(n, 256), THREADS>>>(feat, W1, n);
    k_edge1 <<<cdiv((long long)e * 8, THREADS), THREADS>>>(src, dst, ew, e);
    k_xform2<<<cdiv(n, 256), THREADS>>>(W2, b1, n);
    k_edge2 <<<cdiv((long long)e * 4, THREADS), THREADS>>>(src, dst, ew, out, e);
}